// round 10
// baseline (speedup 1.0000x reference)
#include <cuda_runtime.h>

#define THREADS 256
#define L 2500
#define PATCHES 50
#define TWN 500            // master twiddle table: W_2500^j, j=0..499

__device__ __forceinline__ float2 cmul(float2 a, float2 b) {
    return make_float2(a.x * b.x - a.y * b.y, a.x * b.y + a.y * b.x);
}

// radix-5 constants (w = e^{-2pi i/5})
#define CR1 ( 0.30901699437494742f)
#define CR2 (-0.80901699437494742f)
#define SI1 ( 0.95105651629515357f)
#define SI2 ( 0.58778525229247314f)

// Stockham DIF radix-5 stage, natural-order autosort. WORK = 500 each.
template <int NN, int SS>
__device__ __forceinline__ void stage5(const float2* __restrict__ X, float2* __restrict__ Y,
                                       const float2* __restrict__ tw, int tid) {
    constexpr int M = NN / 5;
    constexpr int STRIDE = 2500 / NN;
    for (int w = tid; w < M * SS; w += THREADS) {
        const int q = w % SS;
        const int p = w / SS;
        float2 a0 = X[q + SS * p];
        float2 a1 = X[q + SS * (p + M)];
        float2 a2 = X[q + SS * (p + 2 * M)];
        float2 a3 = X[q + SS * (p + 3 * M)];
        float2 a4 = X[q + SS * (p + 4 * M)];
        float2 t1 = make_float2(a1.x + a4.x, a1.y + a4.y);
        float2 t2 = make_float2(a2.x + a3.x, a2.y + a3.y);
        float2 t3 = make_float2(a1.x - a4.x, a1.y - a4.y);
        float2 t4 = make_float2(a2.x - a3.x, a2.y - a3.y);
        float2 c0 = make_float2(a0.x + t1.x + t2.x, a0.y + t1.y + t2.y);
        float2 m1 = make_float2(a0.x + CR1 * t1.x + CR2 * t2.x, a0.y + CR1 * t1.y + CR2 * t2.y);
        float2 m2 = make_float2(a0.x + CR2 * t1.x + CR1 * t2.x, a0.y + CR2 * t1.y + CR1 * t2.y);
        float2 s1 = make_float2(SI1 * t3.x + SI2 * t4.x, SI1 * t3.y + SI2 * t4.y);
        float2 s2 = make_float2(SI2 * t3.x - SI1 * t4.x, SI2 * t3.y - SI1 * t4.y);
        float2 c1 = make_float2(m1.x + s1.y, m1.y - s1.x);
        float2 c4 = make_float2(m1.x - s1.y, m1.y + s1.x);
        float2 c2 = make_float2(m2.x + s2.y, m2.y - s2.x);
        float2 c3 = make_float2(m2.x - s2.y, m2.y + s2.x);
        float2 w1 = tw[p * STRIDE];
        float2 w2 = cmul(w1, w1);
        float2 w3 = cmul(w2, w1);
        float2 w4 = cmul(w2, w2);
        const int ob = q + SS * 5 * p;
        Y[ob]          = c0;
        Y[ob + SS]     = cmul(c1, w1);
        Y[ob + 2 * SS] = cmul(c2, w2);
        Y[ob + 3 * SS] = cmul(c3, w3);
        Y[ob + 4 * SS] = cmul(c4, w4);
    }
}

// Final radix-4 DIF butterfly (twiddle-free), in registers.
__device__ __forceinline__ void r4(const float2* __restrict__ A, int q,
                                   float2& z0, float2& z1, float2& z2, float2& z3) {
    float2 a0 = A[q], a1 = A[q + 625], a2 = A[q + 1250], a3 = A[q + 1875];
    float2 e0 = make_float2(a0.x + a2.x, a0.y + a2.y);
    float2 e1 = make_float2(a0.x - a2.x, a0.y - a2.y);
    float2 o0 = make_float2(a1.x + a3.x, a1.y + a3.y);
    float2 o1 = make_float2(a1.x - a3.x, a1.y - a3.y);
    z0 = make_float2(e0.x + o0.x, e0.y + o0.y);   // Z[q]
    z1 = make_float2(e1.x + o1.y, e1.y - o1.x);   // Z[q+625]   (e1 - i*o1)
    z2 = make_float2(e0.x - o0.x, e0.y - o0.y);   // Z[q+1250]
    z3 = make_float2(e1.x - o1.y, e1.y + o1.x);   // Z[q+1875]  (e1 + i*o1)
}

// Tie-aware insert into a sorted triple: value desc, index asc on ties
// (= jax.lax.top_k ordering). Guard-first: common miss costs one compare.
__device__ __forceinline__ void ins3g(float v, int k,
                                      float& v0, int& i0, float& v1, int& i1,
                                      float& v2, int& i2) {
    if (v > v2 || (v == v2 && k < i2)) {
        if (v > v1 || (v == v1 && k < i1)) {
            v2 = v1; i2 = i1;
            if (v > v0 || (v == v0 && k < i0)) { v1 = v0; i1 = i0; v0 = v; i0 = k; }
            else { v1 = v; i1 = k; }
        } else { v2 = v; i2 = k; }
    }
}

__global__ __launch_bounds__(THREADS)
void TimeSeriesWeighting_kernel(const float* __restrict__ x,
                                const float* __restrict__ wscal,
                                float* __restrict__ out) {
    __shared__ float2 bufA[L];
    __shared__ float2 bufB[L];
    __shared__ float2 tw[TWN];
    __shared__ float mv[2][THREADS / 32][3];
    __shared__ int   mi[2][THREADS / 32][3];
    __shared__ int   top_idx[2][3];

    const int tid = threadIdx.x;
    const long long b0 = 2LL * blockIdx.x;

    // Pack two batches' head-0 rows: z = x_a + i*x_b (rows 30000 floats apart, 16B-aligned)
    const float4* sa = reinterpret_cast<const float4*>(x + b0 * 30000);
    const float4* sb = reinterpret_cast<const float4*>(x + (b0 + 1) * 30000);
    for (int i = tid; i < 625; i += THREADS) {
        float4 va = sa[i], vb = sb[i];
        int j = i * 4;
        bufA[j]     = make_float2(va.x, vb.x);
        bufA[j + 1] = make_float2(va.y, vb.y);
        bufA[j + 2] = make_float2(va.z, vb.z);
        bufA[j + 3] = make_float2(va.w, vb.w);
    }
    // Master twiddle table (MUFU sincos; ranking-safe, measured rel_err 0.0)
    for (int j = tid; j < TWN; j += THREADS) {
        float sn, cs;
        __sincosf(-6.283185307179586f * (float)j * (1.0f / 2500.0f), &sn, &cs);
        tw[j] = make_float2(cs, sn);
    }
    __syncthreads();

    // 2500 = 5*5*5*5*4 mixed-radix Stockham (autosort -> natural order)
    stage5<2500, 1>(bufA, bufB, tw, tid);  __syncthreads();
    stage5<500, 5>(bufB, bufA, tw, tid);   __syncthreads();
    stage5<100, 25>(bufA, bufB, tw, tid);  __syncthreads();
    stage5<20, 125>(bufB, bufA, tw, tid);  __syncthreads();

    // Fused final radix-4 + conjugate-split + power + top-3, all in registers.
    // Butterflies q and 625-q jointly produce the 4 conjugate pairs covering
    // half-bins {q, 625-q, 625+q, 1250-q}:
    //   pw_a[k] ∝ |Z[k]+conj(Z[2500-k])|^2 , pw_b[k] ∝ |Z[k]-conj(Z[2500-k])|^2
    float av0 = -1.0f, av1 = -1.0f, av2 = -1.0f;
    float bv0 = -1.0f, bv1 = -1.0f, bv2 = -1.0f;
    int ai0 = 0x7fffffff, ai1 = 0x7fffffff, ai2 = 0x7fffffff;
    int bi0 = 0x7fffffff, bi1 = 0x7fffffff, bi2 = 0x7fffffff;

    #define PAIRPOW(zk, zm, kk) do {                                          \
        float sx = (zk).x + (zm).x, sy = (zk).y - (zm).y;                     \
        float dx = (zk).x - (zm).x, dy = (zk).y + (zm).y;                     \
        ins3g(sx * sx + sy * sy, (kk), av0, ai0, av1, ai1, av2, ai2);         \
        ins3g(dx * dx + dy * dy, (kk), bv0, bi0, bv1, bi1, bv2, bi2);         \
    } while (0)

    for (int w = tid; w < 313; w += THREADS) {
        if (w == 0) {
            // self-paired butterfly 0: bins 0, 625 (pairs with 1875), 1250
            float2 z0, z1, z2, z3;
            r4(bufA, 0, z0, z1, z2, z3);
            PAIRPOW(z0, z0, 0);
            PAIRPOW(z1, z3, 625);
            PAIRPOW(z2, z2, 1250);
        } else {
            const int q = w;              // 1..312
            float2 q0, q1, q2, q3, p0, p1, p2, p3;
            r4(bufA, q, q0, q1, q2, q3);
            r4(bufA, 625 - q, p0, p1, p2, p3);
            PAIRPOW(q0, p3, q);           // Z[q]      & Z[2500-q]
            PAIRPOW(p0, q3, 625 - q);     // Z[625-q]  & Z[1875+q]
            PAIRPOW(q1, p2, 625 + q);     // Z[625+q]  & Z[1875-q]
            PAIRPOW(p1, q2, 1250 - q);    // Z[1250-q] & Z[1250+q]
        }
    }
    #undef PAIRPOW

    // Warp-level merge of sorted triples (shuffles converged, inserts after)
    #pragma unroll
    for (int off = 16; off > 0; off >>= 1) {
        float t0 = __shfl_down_sync(0xffffffffu, av0, off);
        int   j0 = __shfl_down_sync(0xffffffffu, ai0, off);
        float t1 = __shfl_down_sync(0xffffffffu, av1, off);
        int   j1 = __shfl_down_sync(0xffffffffu, ai1, off);
        float t2 = __shfl_down_sync(0xffffffffu, av2, off);
        int   j2 = __shfl_down_sync(0xffffffffu, ai2, off);
        float u0 = __shfl_down_sync(0xffffffffu, bv0, off);
        int   l0 = __shfl_down_sync(0xffffffffu, bi0, off);
        float u1 = __shfl_down_sync(0xffffffffu, bv1, off);
        int   l1 = __shfl_down_sync(0xffffffffu, bi1, off);
        float u2 = __shfl_down_sync(0xffffffffu, bv2, off);
        int   l2 = __shfl_down_sync(0xffffffffu, bi2, off);
        ins3g(t0, j0, av0, ai0, av1, ai1, av2, ai2);
        ins3g(t1, j1, av0, ai0, av1, ai1, av2, ai2);
        ins3g(t2, j2, av0, ai0, av1, ai1, av2, ai2);
        ins3g(u0, l0, bv0, bi0, bv1, bi1, bv2, bi2);
        ins3g(u1, l1, bv0, bi0, bv1, bi1, bv2, bi2);
        ins3g(u2, l2, bv0, bi0, bv1, bi1, bv2, bi2);
    }

    const int wid = tid >> 5;
    if ((tid & 31) == 0) {
        mv[0][wid][0] = av0; mi[0][wid][0] = ai0;
        mv[0][wid][1] = av1; mi[0][wid][1] = ai1;
        mv[0][wid][2] = av2; mi[0][wid][2] = ai2;
        mv[1][wid][0] = bv0; mi[1][wid][0] = bi0;
        mv[1][wid][1] = bv1; mi[1][wid][1] = bi1;
        mv[1][wid][2] = bv2; mi[1][wid][2] = bi2;
    }
    __syncthreads();
    // two parallel CTA-level merges: thread 0 -> batch a, thread 32 -> batch b
    if (tid == 0 || tid == 32) {
        const int gg = (tid == 32);
        float f0 = mv[gg][0][0], f1 = mv[gg][0][1], f2 = mv[gg][0][2];
        int   e0 = mi[gg][0][0], e1 = mi[gg][0][1], e2 = mi[gg][0][2];
        #pragma unroll
        for (int wq = 1; wq < THREADS / 32; wq++) {
            ins3g(mv[gg][wq][0], mi[gg][wq][0], f0, e0, f1, e1, f2, e2);
            ins3g(mv[gg][wq][1], mi[gg][wq][1], f0, e0, f1, e1, f2, e2);
            ins3g(mv[gg][wq][2], mi[gg][wq][2], f0, e0, f1, e1, f2, e2);
        }
        top_idx[gg][0] = e0; top_idx[gg][1] = e1; top_idx[gg][2] = e2;
    }
    __syncthreads();

    // Full-spectrum ranks {0, 2} from half-spectrum top-3 with pair multiplicity:
    // DC (0) and Nyquist (1250) appear once; other bins twice (k, 2500-k).
    const int g = tid >> 7;        // threads [0,128) -> batch a, [128,256) -> batch b
    const int lt = tid & 127;
    const int h0 = top_idx[g][0], h1 = top_idx[g][1], h2 = top_idx[g][2];
    const bool h0_pair = (h0 != 0 && h0 != 1250);
    const bool h1_pair = (h1 != 0 && h1 != 1250);
    const int ka = h0;
    const int kb = (h0_pair || h1_pair) ? h1 : h2;

    if (lt < PATCHES) {
        const float wgt = 12.0f * wscal[0];  // N * weights
        const int start = lt * 50;
        int cnt = 0;
        if (ka != 0) {
            int p = L / ka;
            int fm = ((start + p - 1) / p) * p;
            cnt += (fm < start + 50);
        }
        if (kb != 0) {
            int p = L / kb;
            int fm = ((start + p - 1) / p) * p;
            cnt += (fm < start + 50);
        }
        out[(b0 + g) * PATCHES + lt] = wgt * (float)cnt;
    }
}

extern "C" void kernel_launch(void* const* d_in, const int* in_sizes, int n_in,
                              void* d_out, int out_size) {
    const float* x = (const float*)d_in[0];
    const float* w = (const float*)d_in[1];
    int xs = in_sizes[0];
    if (n_in >= 2 && in_sizes[0] < in_sizes[1]) {  // order-robust: scalar vs big tensor
        x = (const float*)d_in[1];
        w = (const float*)d_in[0];
        xs = in_sizes[1];
    }
    const int B = xs / (12 * L);   // 1024
    TimeSeriesWeighting_kernel<<<B / 2, THREADS>>>(x, w, (float*)d_out);
}

// round 11
// speedup vs baseline: 1.2280x; 1.2280x over previous
#include <cuda_runtime.h>

#define THREADS 256
#define L 2500
#define HALF 1251          // bins 0..1250
#define PATCHES 50
#define TWN 500            // master twiddle table: W_2500^j, j=0..499
#define GROUP 128          // threads per batch in the search phase

__device__ __forceinline__ float2 cmul(float2 a, float2 b) {
    return make_float2(a.x * b.x - a.y * b.y, a.x * b.y + a.y * b.x);
}

// radix-5 constants (w = e^{-2pi i/5})
#define CR1 ( 0.30901699437494742f)
#define CR2 (-0.80901699437494742f)
#define SI1 ( 0.95105651629515357f)
#define SI2 ( 0.58778525229247314f)

// Stockham DIF radix-5 stage, natural-order autosort. WORK = 500 each.
template <int NN, int SS>
__device__ __forceinline__ void stage5(const float2* __restrict__ X, float2* __restrict__ Y,
                                       const float2* __restrict__ tw, int tid) {
    constexpr int M = NN / 5;
    constexpr int STRIDE = 2500 / NN;
    for (int w = tid; w < M * SS; w += THREADS) {
        const int q = w % SS;
        const int p = w / SS;
        float2 a0 = X[q + SS * p];
        float2 a1 = X[q + SS * (p + M)];
        float2 a2 = X[q + SS * (p + 2 * M)];
        float2 a3 = X[q + SS * (p + 3 * M)];
        float2 a4 = X[q + SS * (p + 4 * M)];
        float2 t1 = make_float2(a1.x + a4.x, a1.y + a4.y);
        float2 t2 = make_float2(a2.x + a3.x, a2.y + a3.y);
        float2 t3 = make_float2(a1.x - a4.x, a1.y - a4.y);
        float2 t4 = make_float2(a2.x - a3.x, a2.y - a3.y);
        float2 c0 = make_float2(a0.x + t1.x + t2.x, a0.y + t1.y + t2.y);
        float2 m1 = make_float2(a0.x + CR1 * t1.x + CR2 * t2.x, a0.y + CR1 * t1.y + CR2 * t2.y);
        float2 m2 = make_float2(a0.x + CR2 * t1.x + CR1 * t2.x, a0.y + CR2 * t1.y + CR1 * t2.y);
        float2 s1 = make_float2(SI1 * t3.x + SI2 * t4.x, SI1 * t3.y + SI2 * t4.y);
        float2 s2 = make_float2(SI2 * t3.x - SI1 * t4.x, SI2 * t3.y - SI1 * t4.y);
        float2 c1 = make_float2(m1.x + s1.y, m1.y - s1.x);
        float2 c4 = make_float2(m1.x - s1.y, m1.y + s1.x);
        float2 c2 = make_float2(m2.x + s2.y, m2.y - s2.x);
        float2 c3 = make_float2(m2.x - s2.y, m2.y + s2.x);
        float2 w1 = tw[p * STRIDE];
        float2 w2 = cmul(w1, w1);
        float2 w3 = cmul(w2, w1);
        float2 w4 = cmul(w2, w2);
        const int ob = q + SS * 5 * p;
        Y[ob]          = c0;
        Y[ob + SS]     = cmul(c1, w1);
        Y[ob + 2 * SS] = cmul(c2, w2);
        Y[ob + 3 * SS] = cmul(c3, w3);
        Y[ob + 4 * SS] = cmul(c4, w4);
    }
}

// Final radix-4 DIF butterfly (twiddle-free), in registers.
__device__ __forceinline__ void r4(const float2* __restrict__ A, int q,
                                   float2& z0, float2& z1, float2& z2, float2& z3) {
    float2 a0 = A[q], a1 = A[q + 625], a2 = A[q + 1250], a3 = A[q + 1875];
    float2 e0 = make_float2(a0.x + a2.x, a0.y + a2.y);
    float2 e1 = make_float2(a0.x - a2.x, a0.y - a2.y);
    float2 o0 = make_float2(a1.x + a3.x, a1.y + a3.y);
    float2 o1 = make_float2(a1.x - a3.x, a1.y - a3.y);
    z0 = make_float2(e0.x + o0.x, e0.y + o0.y);   // Z[q]
    z1 = make_float2(e1.x + o1.y, e1.y - o1.x);   // Z[q+625]   (e1 - i*o1)
    z2 = make_float2(e0.x - o0.x, e0.y - o0.y);   // Z[q+1250]
    z3 = make_float2(e1.x - o1.y, e1.y + o1.x);   // Z[q+1875]  (e1 + i*o1)
}

__global__ __launch_bounds__(THREADS)
void TimeSeriesWeighting_kernel(const float* __restrict__ x,
                                const float* __restrict__ wscal,
                                float* __restrict__ out) {
    __shared__ float2 bufA[L];
    __shared__ float2 bufB[L];
    __shared__ float2 tw[TWN];
    __shared__ float s_v[THREADS / 32];
    __shared__ int   s_i[THREADS / 32];
    __shared__ int   top_idx[2][3];

    const int tid = threadIdx.x;
    const long long b0 = 2LL * blockIdx.x;

    // Pack two batches' head-0 rows: z = x_a + i*x_b (rows 30000 floats apart, 16B-aligned)
    const float4* sa = reinterpret_cast<const float4*>(x + b0 * 30000);
    const float4* sb = reinterpret_cast<const float4*>(x + (b0 + 1) * 30000);
    for (int i = tid; i < 625; i += THREADS) {
        float4 va = sa[i], vb = sb[i];
        int j = i * 4;
        bufA[j]     = make_float2(va.x, vb.x);
        bufA[j + 1] = make_float2(va.y, vb.y);
        bufA[j + 2] = make_float2(va.z, vb.z);
        bufA[j + 3] = make_float2(va.w, vb.w);
    }
    // Master twiddle table (MUFU sincos; ranking-safe, measured rel_err 0.0)
    for (int j = tid; j < TWN; j += THREADS) {
        float sn, cs;
        __sincosf(-6.283185307179586f * (float)j * (1.0f / 2500.0f), &sn, &cs);
        tw[j] = make_float2(cs, sn);
    }
    __syncthreads();

    // 2500 = 5*5*5*5*4 mixed-radix Stockham (autosort -> natural order)
    stage5<2500, 1>(bufA, bufB, tw, tid);  __syncthreads();
    stage5<500, 5>(bufB, bufA, tw, tid);   __syncthreads();
    stage5<100, 25>(bufA, bufB, tw, tid);  __syncthreads();
    stage5<20, 125>(bufB, bufA, tw, tid);  __syncthreads();

    // Fused final radix-4 + conjugate-split + power -> pa/pb in smem.
    // Butterflies q and 625-q jointly produce the 4 conjugate pairs covering
    // half-bins {q, 625-q, 625+q, 1250-q} (verified, R10 passed correctness):
    //   pw_a[k] ∝ |Z[k]+conj(Z[2500-k])|^2 , pw_b[k] ∝ |Z[k]-conj(Z[2500-k])|^2
    float* pa = reinterpret_cast<float*>(bufB);   // 1251 floats
    float* pb = pa + 1280;                        // 1251 floats (bufB = 5000 floats)

    #define PAIRPOW(zk, zm, kk) do {                                          \
        float sx = (zk).x + (zm).x, sy = (zk).y - (zm).y;                     \
        float dx = (zk).x - (zm).x, dy = (zk).y + (zm).y;                     \
        pa[(kk)] = sx * sx + sy * sy;                                         \
        pb[(kk)] = dx * dx + dy * dy;                                         \
    } while (0)

    for (int w = tid; w < 313; w += THREADS) {
        if (w == 0) {
            // self-paired butterfly 0: bins 0, 625 (pairs with 1875), 1250
            float2 z0, z1, z2, z3;
            r4(bufA, 0, z0, z1, z2, z3);
            PAIRPOW(z0, z0, 0);
            PAIRPOW(z1, z3, 625);
            PAIRPOW(z2, z2, 1250);
        } else {
            const int q = w;              // 1..312
            float2 q0, q1, q2, q3, p0, p1, p2, p3;
            r4(bufA, q, q0, q1, q2, q3);
            r4(bufA, 625 - q, p0, p1, p2, p3);
            PAIRPOW(q0, p3, q);           // Z[q]      & Z[2500-q]
            PAIRPOW(p0, q3, 625 - q);     // Z[625-q]  & Z[1875+q]
            PAIRPOW(q1, p2, 625 + q);     // Z[625+q]  & Z[1875-q]
            PAIRPOW(p1, q2, 1250 - q);    // Z[1250-q] & Z[1250+q]
        }
    }
    #undef PAIRPOW
    __syncthreads();

    // Top-3 half-spectrum bins per batch; group 0 = threads 0..127 (batch a),
    // group 1 = threads 128..255 (batch b). 3 exclusion passes (proven fastest).
    const int g = tid >> 7;
    const int lt = tid & 127;
    const float* pw = g ? pb : pa;
    for (int r = 0; r < 3; r++) {
        const int e0 = (r > 0) ? top_idx[g][0] : -1;
        const int e1 = (r > 1) ? top_idx[g][1] : -1;
        float bv = -1.0f;
        int bi = 0x7fffffff;
        for (int k = lt; k < HALF; k += GROUP) {
            if (k == e0 || k == e1) continue;
            float v = pw[k];
            if (v > bv || (v == bv && k < bi)) { bv = v; bi = k; }
        }
        #pragma unroll
        for (int off = 16; off > 0; off >>= 1) {
            float ov = __shfl_down_sync(0xffffffffu, bv, off);
            int   oi = __shfl_down_sync(0xffffffffu, bi, off);
            if (ov > bv || (ov == bv && oi < bi)) { bv = ov; bi = oi; }
        }
        if ((tid & 31) == 0) { s_v[tid >> 5] = bv; s_i[tid >> 5] = bi; }
        __syncthreads();
        if (lt == 0) {
            const int base = g * 4;
            float fv = s_v[base]; int fi = s_i[base];
            #pragma unroll
            for (int wv = 1; wv < 4; wv++) {
                float v2 = s_v[base + wv]; int i2 = s_i[base + wv];
                if (v2 > fv || (v2 == fv && i2 < fi)) { fv = v2; fi = i2; }
            }
            top_idx[g][r] = fi;
        }
        __syncthreads();
    }

    // Full-spectrum ranks {0, 2} from half-spectrum top-3 with pair multiplicity:
    // DC (0) and Nyquist (1250) appear once; other bins twice (k, 2500-k).
    const int h0 = top_idx[g][0], h1 = top_idx[g][1], h2 = top_idx[g][2];
    const bool h0_pair = (h0 != 0 && h0 != 1250);
    const bool h1_pair = (h1 != 0 && h1 != 1250);
    const int ka = h0;
    const int kb = (h0_pair || h1_pair) ? h1 : h2;

    if (lt < PATCHES) {
        const float wgt = 12.0f * wscal[0];  // N * weights
        const int start = lt * 50;
        int cnt = 0;
        if (ka != 0) {
            int p = L / ka;
            int fm = ((start + p - 1) / p) * p;
            cnt += (fm < start + 50);
        }
        if (kb != 0) {
            int p = L / kb;
            int fm = ((start + p - 1) / p) * p;
            cnt += (fm < start + 50);
        }
        out[(b0 + g) * PATCHES + lt] = wgt * (float)cnt;
    }
}

extern "C" void kernel_launch(void* const* d_in, const int* in_sizes, int n_in,
                              void* d_out, int out_size) {
    const float* x = (const float*)d_in[0];
    const float* w = (const float*)d_in[1];
    int xs = in_sizes[0];
    if (n_in >= 2 && in_sizes[0] < in_sizes[1]) {  // order-robust: scalar vs big tensor
        x = (const float*)d_in[1];
        w = (const float*)d_in[0];
        xs = in_sizes[1];
    }
    const int B = xs / (12 * L);   // 1024
    TimeSeriesWeighting_kernel<<<B / 2, THREADS>>>(x, w, (float*)d_out);
}

// round 12
// speedup vs baseline: 1.3919x; 1.1335x over previous
#include <cuda_runtime.h>

#define THREADS 256
#define L 2500
#define HALF 1251          // bins 0..1250
#define PATCHES 50
#define TWN 500            // master twiddle table: W_2500^j, j=0..499
#define GROUP 128          // threads per batch in the search phase

__device__ __forceinline__ float2 cmul(float2 a, float2 b) {
    return make_float2(a.x * b.x - a.y * b.y, a.x * b.y + a.y * b.x);
}

// radix-5 constants (w = e^{-2pi i/5})
#define CR1 ( 0.30901699437494742f)
#define CR2 (-0.80901699437494742f)
#define SI1 ( 0.95105651629515357f)
#define SI2 ( 0.58778525229247314f)

// Core radix-5 DFT + twiddle + store, shared by all stages.
__device__ __forceinline__ void bf5_store(float2 a0, float2 a1, float2 a2, float2 a3, float2 a4,
                                          float2 w1, float2* __restrict__ Y, int ob, int SS) {
    float2 t1 = make_float2(a1.x + a4.x, a1.y + a4.y);
    float2 t2 = make_float2(a2.x + a3.x, a2.y + a3.y);
    float2 t3 = make_float2(a1.x - a4.x, a1.y - a4.y);
    float2 t4 = make_float2(a2.x - a3.x, a2.y - a3.y);
    float2 c0 = make_float2(a0.x + t1.x + t2.x, a0.y + t1.y + t2.y);
    float2 m1 = make_float2(a0.x + CR1 * t1.x + CR2 * t2.x, a0.y + CR1 * t1.y + CR2 * t2.y);
    float2 m2 = make_float2(a0.x + CR2 * t1.x + CR1 * t2.x, a0.y + CR2 * t1.y + CR1 * t2.y);
    float2 s1 = make_float2(SI1 * t3.x + SI2 * t4.x, SI1 * t3.y + SI2 * t4.y);
    float2 s2 = make_float2(SI2 * t3.x - SI1 * t4.x, SI2 * t3.y - SI1 * t4.y);
    float2 c1 = make_float2(m1.x + s1.y, m1.y - s1.x);
    float2 c4 = make_float2(m1.x - s1.y, m1.y + s1.x);
    float2 c2 = make_float2(m2.x + s2.y, m2.y - s2.x);
    float2 c3 = make_float2(m2.x - s2.y, m2.y + s2.x);
    float2 w2 = cmul(w1, w1);
    float2 w3 = cmul(w2, w1);
    float2 w4 = cmul(w2, w2);
    Y[ob]          = c0;
    Y[ob + SS]     = cmul(c1, w1);
    Y[ob + 2 * SS] = cmul(c2, w2);
    Y[ob + 3 * SS] = cmul(c3, w3);
    Y[ob + 4 * SS] = cmul(c4, w4);
}

// Stockham DIF radix-5 stage, natural-order autosort. WORK = 500 each.
template <int NN, int SS>
__device__ __forceinline__ void stage5(const float2* __restrict__ X, float2* __restrict__ Y,
                                       const float2* __restrict__ tw, int tid) {
    constexpr int M = NN / 5;
    constexpr int STRIDE = 2500 / NN;
    for (int w = tid; w < M * SS; w += THREADS) {
        const int q = w % SS;
        const int p = w / SS;
        bf5_store(X[q + SS * p], X[q + SS * (p + M)], X[q + SS * (p + 2 * M)],
                  X[q + SS * (p + 3 * M)], X[q + SS * (p + 4 * M)],
                  tw[p * STRIDE], Y, q + SS * 5 * p, SS);
    }
}

// Final radix-4 DIF butterfly (twiddle-free), in registers.
__device__ __forceinline__ void r4(const float2* __restrict__ A, int q,
                                   float2& z0, float2& z1, float2& z2, float2& z3) {
    float2 a0 = A[q], a1 = A[q + 625], a2 = A[q + 1250], a3 = A[q + 1875];
    float2 e0 = make_float2(a0.x + a2.x, a0.y + a2.y);
    float2 e1 = make_float2(a0.x - a2.x, a0.y - a2.y);
    float2 o0 = make_float2(a1.x + a3.x, a1.y + a3.y);
    float2 o1 = make_float2(a1.x - a3.x, a1.y - a3.y);
    z0 = make_float2(e0.x + o0.x, e0.y + o0.y);   // Z[q]
    z1 = make_float2(e1.x + o1.y, e1.y - o1.x);   // Z[q+625]   (e1 - i*o1)
    z2 = make_float2(e0.x - o0.x, e0.y - o0.y);   // Z[q+1250]
    z3 = make_float2(e1.x - o1.y, e1.y + o1.x);   // Z[q+1875]  (e1 + i*o1)
}

__global__ __launch_bounds__(THREADS)
void TimeSeriesWeighting_kernel(const float* __restrict__ x,
                                const float* __restrict__ wscal,
                                float* __restrict__ out) {
    __shared__ float2 bufA[L];
    __shared__ float2 bufB[L];
    __shared__ float2 tw[TWN];
    __shared__ float s_v[THREADS / 32];
    __shared__ int   s_i[THREADS / 32];
    __shared__ int   top_idx[2][3];

    const int tid = threadIdx.x;
    const long long b0 = 2LL * blockIdx.x;

    // Master twiddle table (MUFU sincos; ranking-safe, measured rel_err 0.0)
    for (int j = tid; j < TWN; j += THREADS) {
        float sn, cs;
        __sincosf(-6.283185307179586f * (float)j * (1.0f / 2500.0f), &sn, &cs);
        tw[j] = make_float2(cs, sn);
    }
    __syncthreads();

    // Fused load + stage 1 (NN=2500, SS=1): read the two head-0 rows straight
    // from global (coalesced: consecutive p across a warp), pack z = x_a + i*x_b,
    // butterfly, write to bufB. No gmem->smem staging pass.
    const float* xa = x + b0 * 30000;
    const float* xb = xa + 30000;
    for (int p = tid; p < 500; p += THREADS) {
        float2 a0 = make_float2(xa[p],        xb[p]);
        float2 a1 = make_float2(xa[p +  500], xb[p +  500]);
        float2 a2 = make_float2(xa[p + 1000], xb[p + 1000]);
        float2 a3 = make_float2(xa[p + 1500], xb[p + 1500]);
        float2 a4 = make_float2(xa[p + 2000], xb[p + 2000]);
        bf5_store(a0, a1, a2, a3, a4, tw[p], bufB, 5 * p, 1);
    }
    __syncthreads();

    // Remaining Stockham stages (natural-order autosort)
    stage5<500, 5>(bufB, bufA, tw, tid);   __syncthreads();
    stage5<100, 25>(bufA, bufB, tw, tid);  __syncthreads();
    stage5<20, 125>(bufB, bufA, tw, tid);  __syncthreads();

    // Fused final radix-4 + conjugate-split + power -> pa/pb in smem.
    // Butterflies q and 625-q jointly produce the 4 conjugate pairs covering
    // half-bins {q, 625-q, 625+q, 1250-q} (verified in R10/R11):
    //   pw_a[k] ∝ |Z[k]+conj(Z[2500-k])|^2 , pw_b[k] ∝ |Z[k]-conj(Z[2500-k])|^2
    float* pa = reinterpret_cast<float*>(bufB);   // 1251 floats
    float* pb = pa + 1280;                        // 1251 floats (bufB = 5000 floats)

    #define PAIRPOW(zk, zm, kk) do {                                          \
        float sx = (zk).x + (zm).x, sy = (zk).y - (zm).y;                     \
        float dx = (zk).x - (zm).x, dy = (zk).y + (zm).y;                     \
        pa[(kk)] = sx * sx + sy * sy;                                         \
        pb[(kk)] = dx * dx + dy * dy;                                         \
    } while (0)

    for (int w = tid; w < 313; w += THREADS) {
        if (w == 0) {
            // self-paired butterfly 0: bins 0, 625 (pairs with 1875), 1250
            float2 z0, z1, z2, z3;
            r4(bufA, 0, z0, z1, z2, z3);
            PAIRPOW(z0, z0, 0);
            PAIRPOW(z1, z3, 625);
            PAIRPOW(z2, z2, 1250);
        } else {
            const int q = w;              // 1..312
            float2 q0, q1, q2, q3, p0, p1, p2, p3;
            r4(bufA, q, q0, q1, q2, q3);
            r4(bufA, 625 - q, p0, p1, p2, p3);
            PAIRPOW(q0, p3, q);           // Z[q]      & Z[2500-q]
            PAIRPOW(p0, q3, 625 - q);     // Z[625-q]  & Z[1875+q]
            PAIRPOW(q1, p2, 625 + q);     // Z[625+q]  & Z[1875-q]
            PAIRPOW(p1, q2, 1250 - q);    // Z[1250-q] & Z[1250+q]
        }
    }
    #undef PAIRPOW
    __syncthreads();

    // Top-3 half-spectrum bins per batch; group 0 = threads 0..127 (batch a),
    // group 1 = threads 128..255 (batch b). 3 exclusion passes (proven fastest).
    const int g = tid >> 7;
    const int lt = tid & 127;
    const float* pw = g ? pb : pa;
    for (int r = 0; r < 3; r++) {
        const int e0 = (r > 0) ? top_idx[g][0] : -1;
        const int e1 = (r > 1) ? top_idx[g][1] : -1;
        float bv = -1.0f;
        int bi = 0x7fffffff;
        for (int k = lt; k < HALF; k += GROUP) {
            if (k == e0 || k == e1) continue;
            float v = pw[k];
            if (v > bv || (v == bv && k < bi)) { bv = v; bi = k; }
        }
        #pragma unroll
        for (int off = 16; off > 0; off >>= 1) {
            float ov = __shfl_down_sync(0xffffffffu, bv, off);
            int   oi = __shfl_down_sync(0xffffffffu, bi, off);
            if (ov > bv || (ov == bv && oi < bi)) { bv = ov; bi = oi; }
        }
        if ((tid & 31) == 0) { s_v[tid >> 5] = bv; s_i[tid >> 5] = bi; }
        __syncthreads();
        if (lt == 0) {
            const int base = g * 4;
            float fv = s_v[base]; int fi = s_i[base];
            #pragma unroll
            for (int wv = 1; wv < 4; wv++) {
                float v2 = s_v[base + wv]; int i2 = s_i[base + wv];
                if (v2 > fv || (v2 == fv && i2 < fi)) { fv = v2; fi = i2; }
            }
            top_idx[g][r] = fi;
        }
        __syncthreads();
    }

    // Full-spectrum ranks {0, 2} from half-spectrum top-3 with pair multiplicity:
    // DC (0) and Nyquist (1250) appear once; other bins twice (k, 2500-k).
    const int h0 = top_idx[g][0], h1 = top_idx[g][1], h2 = top_idx[g][2];
    const bool h0_pair = (h0 != 0 && h0 != 1250);
    const bool h1_pair = (h1 != 0 && h1 != 1250);
    const int ka = h0;
    const int kb = (h0_pair || h1_pair) ? h1 : h2;

    if (lt < PATCHES) {
        const float wgt = 12.0f * wscal[0];  // N * weights
        const int start = lt * 50;
        int cnt = 0;
        if (ka != 0) {
            int p = L / ka;
            int fm = ((start + p - 1) / p) * p;
            cnt += (fm < start + 50);
        }
        if (kb != 0) {
            int p = L / kb;
            int fm = ((start + p - 1) / p) * p;
            cnt += (fm < start + 50);
        }
        out[(b0 + g) * PATCHES + lt] = wgt * (float)cnt;
    }
}

extern "C" void kernel_launch(void* const* d_in, const int* in_sizes, int n_in,
                              void* d_out, int out_size) {
    const float* x = (const float*)d_in[0];
    const float* w = (const float*)d_in[1];
    int xs = in_sizes[0];
    if (n_in >= 2 && in_sizes[0] < in_sizes[1]) {  // order-robust: scalar vs big tensor
        x = (const float*)d_in[1];
        w = (const float*)d_in[0];
        xs = in_sizes[1];
    }
    const int B = xs / (12 * L);   // 1024
    TimeSeriesWeighting_kernel<<<B / 2, THREADS>>>(x, w, (float*)d_out);
}